// round 15
// baseline (speedup 1.0000x reference)
#include <cuda_runtime.h>
#include <cuda_fp16.h>
#include <cstdint>
#include <math.h>

#define NN    8192
#define KDIM  256
#define CDIM  256
#define FDIM  128
#define KT2   64          // dst-tile width
#define BM    64          // src rows per CTA
#define NT2   (NN / KT2)  // 128 tiles
#define PB2   72          // smem pitch in halfs (36 words == 4 mod 32 -> conflict-free)

// ---- scratch (device globals) ----
__device__ float    g_T  [NN * CDIM];     // transformed [i][h*128+f] fp32 (for k_scores)
__device__ __half   g_Thb[NN * CDIM];     // blocked fp16: [j/64][c(256)][j%64]
__device__ uint4    g_hSRC4[NN * 2];      // per (node,head): {S2, (Es-Fs)2, Fs2, 0} half2
__device__ uint32_t g_hD[2 * 3 * (NN / 2)]; // dst halves [head][arr:D,EmF,F][NN] u32 pairs

__device__ __forceinline__ __half2 u2h(uint32_t u) { return *(__half2*)&u; }

// fp16 m16n8k16 HMMA (portable PTX, sm_80+)
__device__ __forceinline__ void mma16816(float c[4], const uint32_t a[4],
                                         uint32_t b0, uint32_t b1) {
    asm volatile(
        "mma.sync.aligned.m16n8k16.row.col.f32.f16.f16.f32 "
        "{%0,%1,%2,%3}, {%4,%5,%6,%7}, {%8,%9}, {%0,%1,%2,%3};\n"
        : "+f"(c[0]), "+f"(c[1]), "+f"(c[2]), "+f"(c[3])
        : "r"(a[0]), "r"(a[1]), "r"(a[2]), "r"(a[3]), "r"(b0), "r"(b1));
}
__device__ __forceinline__ void ldsm4(uint32_t r[4], uint32_t addr) {
    asm volatile("ldmatrix.sync.aligned.m8n8.x4.shared.b16 {%0,%1,%2,%3}, [%4];"
                 : "=r"(r[0]), "=r"(r[1]), "=r"(r[2]), "=r"(r[3]) : "r"(addr));
}
__device__ __forceinline__ uint32_t smem_u32p(const void* p) {
    return (uint32_t)__cvta_generic_to_shared(p);
}
__device__ __forceinline__ void cpa16(uint32_t d, const void* s) {
    asm volatile("cp.async.cg.shared.global [%0], [%1], 16;" :: "r"(d), "l"(s));
}
#define CPA_COMMIT() asm volatile("cp.async.commit_group;" ::: "memory")
#define CPA_WAIT0()  asm volatile("cp.async.wait_group 0;" ::: "memory")

// ============================================================
// Kernel 1: T = features @ W^T via fp16 HMMA (fp32 accumulate).
// ============================================================
__global__ void __launch_bounds__(256) k_transform(const float* __restrict__ feat,
                                                   const float* __restrict__ W) {
    __shared__ __half Fs[128 * PB2];
    __shared__ __half Ws[64 * PB2];
    const int i0 = blockIdx.x * 128;
    const int c0 = blockIdx.y * 64;
    const int t = threadIdx.x, lane = t & 31, warp = t >> 5;
    const int rg = warp & 3, cb = warp >> 2;
    const int q = lane >> 2, cl = lane & 3, l7 = lane & 7, lg = lane >> 3;

    float acc[2][4][4];
#pragma unroll
    for (int mf = 0; mf < 2; mf++)
#pragma unroll
        for (int nb = 0; nb < 4; nb++)
#pragma unroll
            for (int c = 0; c < 4; c++) acc[mf][nb][c] = 0.f;

    float4 Fpre[8], Wpre[4];
#pragma unroll
    for (int p = 0; p < 8; p++) {
        int fi = t + p * 256;
        Fpre[p] = *(const float4*)&feat[(size_t)(i0 + (fi >> 4)) * KDIM + (fi & 15) * 4];
    }
#pragma unroll
    for (int p = 0; p < 4; p++) {
        int wi = t + p * 256;
        Wpre[p] = *(const float4*)&W[(size_t)(c0 + (wi >> 4)) * KDIM + (wi & 15) * 4];
    }

    const uint32_t fs_b = smem_u32p(Fs);
    const uint32_t ws_b = smem_u32p(Ws);

    for (int kc = 0; kc < 4; kc++) {
#pragma unroll
        for (int p = 0; p < 8; p++) {
            int fi = t + p * 256;
            __half2 h0 = __floats2half2_rn(Fpre[p].x, Fpre[p].y);
            __half2 h1 = __floats2half2_rn(Fpre[p].z, Fpre[p].w);
            *(uint2*)&Fs[(fi >> 4) * PB2 + (fi & 15) * 4] =
                make_uint2(*(uint32_t*)&h0, *(uint32_t*)&h1);
        }
#pragma unroll
        for (int p = 0; p < 4; p++) {
            int wi = t + p * 256;
            __half2 h0 = __floats2half2_rn(Wpre[p].x, Wpre[p].y);
            __half2 h1 = __floats2half2_rn(Wpre[p].z, Wpre[p].w);
            *(uint2*)&Ws[(wi >> 4) * PB2 + (wi & 15) * 4] =
                make_uint2(*(uint32_t*)&h0, *(uint32_t*)&h1);
        }
        if (kc + 1 < 4) {
            const int ko = (kc + 1) * 64;
#pragma unroll
            for (int p = 0; p < 8; p++) {
                int fi = t + p * 256;
                Fpre[p] = *(const float4*)&feat[(size_t)(i0 + (fi >> 4)) * KDIM + ko + (fi & 15) * 4];
            }
#pragma unroll
            for (int p = 0; p < 4; p++) {
                int wi = t + p * 256;
                Wpre[p] = *(const float4*)&W[(size_t)(c0 + (wi >> 4)) * KDIM + ko + (wi & 15) * 4];
            }
        }
        __syncthreads();

#pragma unroll
        for (int kb2 = 0; kb2 < 2; kb2++) {
            uint32_t a[2][2][4];
#pragma unroll
            for (int mf = 0; mf < 2; mf++)
#pragma unroll
                for (int ki = 0; ki < 2; ki++) {
                    int kb = kb2 * 2 + ki;
                    uint32_t addr = fs_b +
                        (uint32_t)(((32 * rg + 16 * mf + l7 + (lg & 1) * 8) * PB2 +
                                    kb * 16 + (lg >> 1) * 8) * 2);
                    ldsm4(a[mf][ki], addr);
                }
#pragma unroll
            for (int nb = 0; nb < 4; nb++) {
                uint32_t baddr = ws_b +
                    (uint32_t)(((32 * cb + 8 * nb + l7) * PB2 + kb2 * 32 + lg * 8) * 2);
                uint32_t b[4];
                ldsm4(b, baddr);
                mma16816(acc[0][nb], a[0][0], b[0], b[1]);
                mma16816(acc[0][nb], a[0][1], b[2], b[3]);
                mma16816(acc[1][nb], a[1][0], b[0], b[1]);
                mma16816(acc[1][nb], a[1][1], b[2], b[3]);
            }
        }
        __syncthreads();
    }

#pragma unroll
    for (int mf = 0; mf < 2; mf++)
#pragma unroll
        for (int nb = 0; nb < 4; nb++) {
            const int row0 = 32 * rg + 16 * mf + q;
            const int row1 = row0 + 8;
            const int colg = c0 + 32 * cb + 8 * nb + 2 * cl;
            *(float2*)&g_T[(size_t)(i0 + row0) * CDIM + colg] =
                make_float2(acc[mf][nb][0], acc[mf][nb][1]);
            *(float2*)&g_T[(size_t)(i0 + row1) * CDIM + colg] =
                make_float2(acc[mf][nb][2], acc[mf][nb][3]);
#pragma unroll
            for (int c4 = 0; c4 < 4; c4++) {
                const int row = (c4 < 2) ? row0 : row1;
                const int cg = colg + (c4 & 1);
                g_Thb[(size_t)((i0 + row) >> 6) * 16384 + cg * 64 + (row & 63)] =
                    __float2half_rn(acc[mf][nb][c4]);
            }
        }
}

// ============================================================
// Kernel 2: scores + packed half2 separable-exp factors
// ============================================================
__global__ void __launch_bounds__(256) k_scores(const float* __restrict__ attn_src,
                                                const float* __restrict__ attn_dst) {
    __shared__ float as_[CDIM], ad_[CDIM];
    int t = threadIdx.x;
    as_[t] = attn_src[t];
    ad_[t] = attn_dst[t];
    __syncthreads();
    int warp = t >> 5, lane = t & 31;
    int row = blockIdx.x * 8 + warp;

    float s0 = 0.f, s1 = 0.f, d0 = 0.f, d1 = 0.f;
#pragma unroll
    for (int f = lane; f < FDIM; f += 32) {
        float t0 = g_T[(size_t)row * CDIM + f];
        float t1 = g_T[(size_t)row * CDIM + FDIM + f];
        s0 = fmaf(t0, as_[f], s0);
        d0 = fmaf(t0, ad_[f], d0);
        s1 = fmaf(t1, as_[FDIM + f], s1);
        d1 = fmaf(t1, ad_[FDIM + f], d1);
    }
#pragma unroll
    for (int o = 16; o > 0; o >>= 1) {
        s0 += __shfl_xor_sync(0xFFFFFFFFu, s0, o);
        s1 += __shfl_xor_sync(0xFFFFFFFFu, s1, o);
        d0 += __shfl_xor_sync(0xFFFFFFFFu, d0, o);
        d1 += __shfl_xor_sync(0xFFFFFFFFu, d1, o);
    }
    if (lane == 0) {
        float Ss[2] = {s0, s1}, Dd[2] = {d0, d1};
        __half* hb = (__half*)g_hD;
#pragma unroll
        for (int h = 0; h < 2; h++) {
            float S = Ss[h], D = Dd[h];
            float Es = expf(S), Fs = expf(0.2f * S);
            float Ed = expf(D), Fd = expf(0.2f * D);
            __half2 a = __floats2half2_rn(S, S);
            __half2 b = __floats2half2_rn(Es - Fs, Es - Fs);
            __half2 c = __floats2half2_rn(Fs, Fs);
            uint4 u;
            u.x = *(uint32_t*)&a; u.y = *(uint32_t*)&b; u.z = *(uint32_t*)&c; u.w = 0;
            g_hSRC4[row * 2 + h] = u;
            hb[(h * 3 + 0) * NN + row] = __float2half_rn(D);
            hb[(h * 3 + 1) * NN + row] = __float2half_rn(Ed - Fd);
            hb[(h * 3 + 2) * NN + row] = __float2half_rn(Fd);
        }
    }
}

// ============================================================
// Kernel 3: fp16 aggregation; pipelined build(t+1) || mma(t);
// cp.async T-tiles; MMA row-sums split across cs==2/cs==3 warps.
// ============================================================
#define TS_SZ   (264 * PB2)
#define PS_SZ   (128 * PB2)
#define DS_WOFF ((2 * TS_SZ + 2 * PS_SZ) / 2)
#define SMEM_DYN (112896 + 1536 + 256)

__global__ void __launch_bounds__(512, 1) k_aggregate(const int* __restrict__ adj,
                                                      float* __restrict__ out) {
    extern __shared__ __align__(16) __half dyn[];
    uint32_t* dS = (uint32_t*)dyn + DS_WOFF;   // [slot][head][arr][32] u32
    __shared__ float lsm[2][2][BM];            // [part][head][row]

    const int t = threadIdx.x;
    const int i0 = blockIdx.x * BM;
    const int lane = t & 31, warp = t >> 5;
    const int q = lane >> 2, cl = lane & 3;
    const int l7 = lane & 7, lg = lane >> 3;

    const int rg = warp & 1;
    const int h  = (warp >> 1) & 1;
    const int cs = warp >> 2;

    const int br = t >> 3, bjq = t & 7;
    const int* arow = adj + (size_t)(i0 + br) * NN;

    uint4 su[2];
    su[0] = g_hSRC4[(i0 + br) * 2 + 0];
    su[1] = g_hSRC4[(i0 + br) * 2 + 1];

    // cp.async Ts(0) -> buffer 0
    {
        const uint32_t dstb = smem_u32p(dyn);
#pragma unroll
        for (int p = 0; p < 4; p++) {
            int chunk = t + p * 512;
            int c = chunk >> 3, kc = chunk & 7;
            cpa16(dstb + (uint32_t)((c * PB2 + kc * 8) * 2), g_Thb + (size_t)chunk * 8);
        }
        CPA_COMMIT();
    }
    // adjacency(0)
    int4 areg[2];
    areg[0] = *(const int4*)(arow + 4 * bjq);
    areg[1] = *(const int4*)(arow + 4 * (bjq + 8));

    // dS: stage slots 0 and 1 (tiles 0,1); prefetch tile 2
    const int sh2 = t / 96, sar = (t % 96) / 32, sw = t % 32;
    const uint32_t* gDp = g_hD + (sh2 * 3 + sar) * 4096;
    uint32_t dpre = 0;
    if (t < 192) {
        dS[((0 * 2 + sh2) * 3 + sar) * 32 + sw] = gDp[sw];
        dS[((1 * 2 + sh2) * 3 + sar) * 32 + sw] = gDp[32 + sw];
        dpre = gDp[64 + sw];
    }
    // ones rows (256..263) in both Ts buffers
    if (t < 256) {
        int buf = t >> 7, rr = 256 + ((t >> 4) & 7), seg = t & 15;
        __half2 v = (rr == 256) ? __floats2half2_rn(1.f, 1.f)
                                : __floats2half2_rn(0.f, 0.f);
        uint32_t u = *(uint32_t*)&v;
        *(uint2*)(dyn + buf * TS_SZ + rr * PB2 + seg * 4) = make_uint2(u, u);
    }

    float acc[2][4][4];
    float accl[2][4];
#pragma unroll
    for (int mf = 0; mf < 2; mf++) {
#pragma unroll
        for (int nb = 0; nb < 4; nb++)
#pragma unroll
            for (int c = 0; c < 4; c++) acc[mf][nb][c] = 0.f;
#pragma unroll
        for (int c = 0; c < 4; c++) accl[mf][c] = 0.f;
    }

    __syncthreads();   // dS slots + ones rows visible

    // ---- prologue: build P(0) -> Ps[0] ----
    {
        __half* Ps0 = dyn + 2 * TS_SZ;
#pragma unroll
        for (int hh = 0; hh < 2; hh++) {
            const __half2 S2   = u2h(su[hh].x);
            const __half2 sEmF = u2h(su[hh].y);
            const __half2 sF   = u2h(su[hh].z);
            const uint32_t* db = dS + (0 * 2 + hh) * 3 * 32;
            const __half2 zero = __floats2half2_rn(0.f, 0.f);
#pragma unroll
            for (int g = 0; g < 2; g++) {
                const int j4 = bjq + 8 * g;
                uint2 Du = *(const uint2*)(db + 2 * j4);
                uint2 Eu = *(const uint2*)(db + 32 + 2 * j4);
                uint2 Fu = *(const uint2*)(db + 64 + 2 * j4);
                const int* av = (const int*)&areg[g];
                uint32_t outp[2];
#pragma unroll
                for (int pp = 0; pp < 2; pp++) {
                    uint32_t Dw = pp ? Du.y : Du.x;
                    uint32_t Ew = pp ? Eu.y : Eu.x;
                    uint32_t Fw = pp ? Fu.y : Fu.x;
                    __half2 cc = __hadd2(S2, u2h(Dw));
                    __half2 m  = __hge2(cc, zero);
                    __half2 fs = __hfma2(m, sEmF, sF);
                    __half2 fd = __hfma2(m, u2h(Ew), u2h(Fw));
                    __half2 am = __floats2half2_rn(av[2 * pp] > 0 ? 1.f : 0.f,
                                                   av[2 * pp + 1] > 0 ? 1.f : 0.f);
                    __half2 v = __hmul2(__hmul2(fs, fd), am);
                    outp[pp] = *(uint32_t*)&v;
                }
                *(uint2*)(Ps0 + (hh * 64 + br) * PB2 + 4 * j4) = make_uint2(outp[0], outp[1]);
            }
        }
    }
    // adjacency(1)
    areg[0] = *(const int4*)(arow + KT2 + 4 * bjq);
    areg[1] = *(const int4*)(arow + KT2 + 4 * (bjq + 8));

    CPA_WAIT0();
    __syncthreads();   // Ts[0] + Ps[0] visible

    for (int tile = 0; tile < NT2; ++tile) {
        const int s = tile & 1;
        __half* Ts = dyn + s * TS_SZ;
        __half* Ps = dyn + 2 * TS_SZ + s * PS_SZ;

        // issue cp.async Ts(t+1) -> other buffer (overlaps everything below)
        if (tile + 1 < NT2) {
            const uint32_t dstb = smem_u32p(dyn + (s ^ 1) * TS_SZ);
            const __half* src = g_Thb + (size_t)(tile + 1) * 16384;
#pragma unroll
            for (int p = 0; p < 4; p++) {
                int chunk = t + p * 512;
                int c = chunk >> 3, kc = chunk & 7;
                cpa16(dstb + (uint32_t)((c * PB2 + kc * 8) * 2), src + (size_t)chunk * 8);
            }
            CPA_COMMIT();
        }

        // ---- build P(t+1) -> Ps[s^1] (same interval as mma(t)) ----
        int4 anext[2];
        if (tile + 1 < NT2) {
            __half* Pn = dyn + 2 * TS_SZ + (s ^ 1) * PS_SZ;
#pragma unroll
            for (int hh = 0; hh < 2; hh++) {
                const __half2 S2   = u2h(su[hh].x);
                const __half2 sEmF = u2h(su[hh].y);
                const __half2 sF   = u2h(su[hh].z);
                const uint32_t* db = dS + (((tile + 1) & 1) * 2 + hh) * 3 * 32;
                const __half2 zero = __floats2half2_rn(0.f, 0.f);
#pragma unroll
                for (int g = 0; g < 2; g++) {
                    const int j4 = bjq + 8 * g;
                    uint2 Du = *(const uint2*)(db + 2 * j4);
                    uint2 Eu = *(const uint2*)(db + 32 + 2 * j4);
                    uint2 Fu = *(const uint2*)(db + 64 + 2 * j4);
                    const int* av = (const int*)&areg[g];
                    uint32_t outp[2];
#pragma unroll
                    for (int pp = 0; pp < 2; pp++) {
                        uint32_t Dw = pp ? Du.y : Du.x;
                        uint32_t Ew = pp ? Eu.y : Eu.x;
                        uint32_t Fw = pp ? Fu.y : Fu.x;
                        __half2 cc = __hadd2(S2, u2h(Dw));
                        __half2 m  = __hge2(cc, zero);
                        __half2 fs = __hfma2(m, sEmF, sF);
                        __half2 fd = __hfma2(m, u2h(Ew), u2h(Fw));
                        __half2 am = __floats2half2_rn(av[2 * pp] > 0 ? 1.f : 0.f,
                                                       av[2 * pp + 1] > 0 ? 1.f : 0.f);
                        __half2 v = __hmul2(__hmul2(fs, fd), am);
                        outp[pp] = *(uint32_t*)&v;
                    }
                    *(uint2*)(Pn + (hh * 64 + br) * PB2 + 4 * j4) = make_uint2(outp[0], outp[1]);
                }
            }
            // prefetch adjacency(t+2)
            if (tile + 2 < NT2) {
                const int jb = (tile + 2) * KT2;
                anext[0] = *(const int4*)(arow + jb + 4 * bjq);
                anext[1] = *(const int4*)(arow + jb + 4 * (bjq + 8));
            }
        }
        // stage dS(t+2) -> slot t&1; prefetch dS(t+3)
        if (t < 192 && tile + 2 < NT2) {
            dS[((s)*2*3 + (sh2)*3 + sar) * 32 + sw] = dpre;   // slot s = (t+2)&1
            if (tile + 3 < NT2) dpre = gDp[(tile + 3) * 32 + sw];
        }

        // ---- HMMA phase on Ts[s], Ps[s] ----
        {
            const uint32_t ts_b = smem_u32p(Ts);
            const uint32_t ps_b = smem_u32p(Ps) + (uint32_t)(h * 64 * PB2 * 2);
#pragma unroll
            for (int kb2 = 0; kb2 < 2; kb2++) {
                uint32_t a[2][2][4];
#pragma unroll
                for (int mf = 0; mf < 2; mf++)
#pragma unroll
                    for (int ki = 0; ki < 2; ki++) {
                        int kb = kb2 * 2 + ki;
                        uint32_t addr = ps_b +
                            (uint32_t)(((32 * rg + 16 * mf + l7 + (lg & 1) * 8) * PB2 +
                                        kb * 16 + (lg >> 1) * 8) * 2);
                        ldsm4(a[mf][ki], addr);
                    }
#pragma unroll
                for (int nb = 0; nb < 4; nb++) {
                    int ncol = h * FDIM + cs * 32 + nb * 8;
                    uint32_t baddr = ts_b +
                        (uint32_t)(((ncol + l7) * PB2 + kb2 * 32 + lg * 8) * 2);
                    uint32_t b[4];
                    ldsm4(b, baddr);
                    mma16816(acc[0][nb], a[0][0], b[0], b[1]);
                    mma16816(acc[0][nb], a[0][1], b[2], b[3]);
                    mma16816(acc[1][nb], a[1][0], b[0], b[1]);
                    mma16816(acc[1][nb], a[1][1], b[2], b[3]);
                }
                if (cs == kb2 + 2) {   // ones-block split: kb2=0 -> cs2, kb2=1 -> cs3
                    uint32_t baddr = ts_b +
                        (uint32_t)(((256 + l7) * PB2 + kb2 * 32 + lg * 8) * 2);
                    uint32_t b[4];
                    ldsm4(b, baddr);
                    mma16816(accl[0], a[0][0], b[0], b[1]);
                    mma16816(accl[0], a[0][1], b[2], b[3]);
                    mma16816(accl[1], a[1][0], b[0], b[1]);
                    mma16816(accl[1], a[1][1], b[2], b[3]);
                }
            }
        }

        areg[0] = anext[0];
        areg[1] = anext[1];

        CPA_WAIT0();       // Ts(t+1) complete
        __syncthreads();   // Ts[s^1] + Ps[s^1] visible for next iter
    }

    // ---- distribute partial row sums ----
    if (cs >= 2 && cl == 0) {
#pragma unroll
        for (int mf = 0; mf < 2; mf++) {
            lsm[cs - 2][h][32 * rg + 16 * mf + q]     = accl[mf][0];
            lsm[cs - 2][h][32 * rg + 16 * mf + q + 8] = accl[mf][2];
        }
    }
    __syncthreads();

    // ---- epilogue ----
    float* ex = (float*)dyn;
    if (h == 1) {
#pragma unroll
        for (int mf = 0; mf < 2; mf++) {
            const int rowA = 32 * rg + 16 * mf + q;
            const int rowB = rowA + 8;
            const float lA = lsm[0][1][rowA] + lsm[1][1][rowA];
            const float lB = lsm[0][1][rowB] + lsm[1][1][rowB];
            const float iA = (lA > 0.f) ? 1.f / lA : 0.f;
            const float iB = (lB > 0.f) ? 1.f / lB : 0.f;
#pragma unroll
            for (int nb = 0; nb < 4; nb++) {
                const int colf = cs * 32 + nb * 8 + 2 * cl;
                *(float2*)&ex[rowA * FDIM + colf] =
                    make_float2(acc[mf][nb][0] * iA, acc[mf][nb][1] * iA);
                *(float2*)&ex[rowB * FDIM + colf] =
                    make_float2(acc[mf][nb][2] * iB, acc[mf][nb][3] * iB);
            }
        }
    }
    __syncthreads();
    if (h == 0) {
#pragma unroll
        for (int mf = 0; mf < 2; mf++) {
            const int rowA = 32 * rg + 16 * mf + q;
            const int rowB = rowA + 8;
            const float lA = lsm[0][0][rowA] + lsm[1][0][rowA];
            const float lB = lsm[0][0][rowB] + lsm[1][0][rowB];
            const float iA = (lA > 0.f) ? 1.f / lA : 0.f;
            const float iB = (lB > 0.f) ? 1.f / lB : 0.f;
#pragma unroll
            for (int nb = 0; nb < 4; nb++) {
                const int colf = cs * 32 + nb * 8 + 2 * cl;
                float2 e0 = *(const float2*)&ex[rowA * FDIM + colf];
                float2 e1 = *(const float2*)&ex[rowB * FDIM + colf];
                float2 oA = make_float2(0.5f * (acc[mf][nb][0] * iA + e0.x),
                                        0.5f * (acc[mf][nb][1] * iA + e0.y));
                float2 oB = make_float2(0.5f * (acc[mf][nb][2] * iB + e1.x),
                                        0.5f * (acc[mf][nb][3] * iB + e1.y));
                *(float2*)&out[(size_t)(i0 + rowA) * FDIM + colf] = oA;
                *(float2*)&out[(size_t)(i0 + rowB) * FDIM + colf] = oB;
            }
        }
    }
}

// ============================================================
extern "C" void kernel_launch(void* const* d_in, const int* in_sizes, int n_in,
                              void* d_out, int out_size) {
    const float* feat = (const float*)d_in[0];
    const int*   adj  = (const int*)d_in[1];
    const float* W    = (const float*)d_in[2];
    const float* asrc = (const float*)d_in[3];
    const float* adst = (const float*)d_in[4];
    float* out = (float*)d_out;

    cudaFuncSetAttribute(k_aggregate, cudaFuncAttributeMaxDynamicSharedMemorySize, SMEM_DYN);

    dim3 g1(NN / 128, CDIM / 64);
    k_transform<<<g1, 256>>>(feat, W);
    k_scores<<<NN / 8, 256>>>(asrc, adst);
    k_aggregate<<<NN / BM, 512, SMEM_DYN>>>(adj, out);
}